// round 3
// baseline (speedup 1.0000x reference)
#include <cuda_runtime.h>
#include <math.h>

#define BB 4
#define SS 1024
#define DD 1024
#define HH 16
#define HDIM 64
#define FF 4096
#define NROWS (BB*SS)           // 4096
#define NHEADS (BB*HH)          // 64
#define LN_EPS 1e-5f
#define ATT_SCALE 0.125f        // 1/sqrt(64)

// ---------------- scratch (static device arrays; no cudaMalloc allowed) --------------
// Reuse: attention output o -> g_y (y dead after V proj); x2 -> g_q (q dead after attn)
__device__ float g_y [NROWS*DD];   // ln1 out, later attention output
__device__ float g_q [NROWS*DD];   // Q, later x2 (post-FFN residual)
__device__ float g_k [NROWS*DD];
__device__ float g_v [NROWS*DD];
__device__ float g_x1[NROWS*DD];   // post-attention residual
__device__ float g_h [NROWS*FF];   // FFN hidden

// ---------------- reduction helpers ----------------
__device__ __forceinline__ float warpSum(float v) {
#pragma unroll
    for (int o = 16; o > 0; o >>= 1) v += __shfl_xor_sync(0xffffffffu, v, o);
    return v;
}
__device__ __forceinline__ float warpMax(float v) {
#pragma unroll
    for (int o = 16; o > 0; o >>= 1) v = fmaxf(v, __shfl_xor_sync(0xffffffffu, v, o));
    return v;
}

// ---------------- LayerNorm over D=1024, one block (256 thr) per row -----------------
__global__ void ln_kernel(const float* __restrict__ in, const float* __restrict__ g,
                          const float* __restrict__ b, float* __restrict__ out) {
    int row = blockIdx.x;
    const float* x = in + (size_t)row * DD;
    int t = threadIdx.x, lane = t & 31, wid = t >> 5;
    float v[4];
#pragma unroll
    for (int i = 0; i < 4; i++) v[i] = x[t + 256 * i];
    float s = v[0] + v[1] + v[2] + v[3];
    float ss = v[0]*v[0] + v[1]*v[1] + v[2]*v[2] + v[3]*v[3];
    s = warpSum(s); ss = warpSum(ss);
    __shared__ float rA[8], rB[8];
    if (lane == 0) { rA[wid] = s; rB[wid] = ss; }
    __syncthreads();
    s  = (lane < 8) ? rA[lane] : 0.f;
    ss = (lane < 8) ? rB[lane] : 0.f;
    s = warpSum(s); ss = warpSum(ss);
    float mean = s * (1.f / DD);
    float var  = ss * (1.f / DD) - mean * mean;
    float rstd = rsqrtf(var + LN_EPS);
    float* o = out + (size_t)row * DD;
#pragma unroll
    for (int i = 0; i < 4; i++) {
        int c = t + 256 * i;
        o[c] = (v[i] - mean) * rstd * g[c] + b[c];
    }
}

// ---------------- mish ----------------
__device__ __forceinline__ float mishf(float x) {
    float sp = (x > 20.f) ? x : log1pf(expf(x));
    return x * tanhf(sp);
}

// ---------------- generic SGEMM: C = epi(A[M,K] @ W[K,N] + bias[N]) ------------------
// EPI: 0 = bias only, 1 = bias + mish, 2 = bias + residual add
template <int EPI>
__global__ __launch_bounds__(256)
void sgemm_kernel(const float* __restrict__ A, const float* __restrict__ W,
                  const float* __restrict__ bias, const float* __restrict__ resid,
                  float* __restrict__ C, int M, int N, int K) {
    __shared__ float As[8][128];
    __shared__ float Bs[8][128];
    int tid = threadIdx.x;
    int bm = blockIdx.y * 128, bn = blockIdx.x * 128;
    int tx = tid & 15, ty = tid >> 4;
    int aRow = tid >> 1, aCol = (tid & 1) * 4;
    int bRow = tid >> 5, bCol = (tid & 31) * 4;
    const float* Ab = A + (size_t)bm * K;
    const float* Wb = W + bn;
    float acc[8][8];
#pragma unroll
    for (int i = 0; i < 8; i++)
#pragma unroll
        for (int j = 0; j < 8; j++) acc[i][j] = 0.f;

    for (int k0 = 0; k0 < K; k0 += 8) {
        float4 av = *(const float4*)(Ab + (size_t)aRow * K + k0 + aCol);
        As[aCol + 0][aRow] = av.x; As[aCol + 1][aRow] = av.y;
        As[aCol + 2][aRow] = av.z; As[aCol + 3][aRow] = av.w;
        float4 bv = *(const float4*)(Wb + (size_t)(k0 + bRow) * N + bCol);
        *(float4*)&Bs[bRow][bCol] = bv;
        __syncthreads();
#pragma unroll
        for (int kk = 0; kk < 8; kk++) {
            float4 a0 = *(const float4*)&As[kk][ty * 8];
            float4 a1 = *(const float4*)&As[kk][ty * 8 + 4];
            float4 b0 = *(const float4*)&Bs[kk][tx * 8];
            float4 b1 = *(const float4*)&Bs[kk][tx * 8 + 4];
            float ar[8] = {a0.x,a0.y,a0.z,a0.w,a1.x,a1.y,a1.z,a1.w};
            float br[8] = {b0.x,b0.y,b0.z,b0.w,b1.x,b1.y,b1.z,b1.w};
#pragma unroll
            for (int i = 0; i < 8; i++)
#pragma unroll
                for (int j = 0; j < 8; j++) acc[i][j] = fmaf(ar[i], br[j], acc[i][j]);
        }
        __syncthreads();
    }
#pragma unroll
    for (int i = 0; i < 8; i++) {
        int row = bm + ty * 8 + i;
#pragma unroll
        for (int j = 0; j < 8; j++) {
            int col = bn + tx * 8 + j;
            float val = acc[i][j] + bias[col];
            if (EPI == 1) val = mishf(val);
            if (EPI == 2) val += resid[(size_t)row * N + col];
            C[(size_t)row * N + col] = val;
        }
    }
}

// ---------------- fused attention: scores + exact 1.5-entmax + P@V -------------------
// One block per (32-query tile, head). Full 32x1024 score rows live in smem.
// smem layout (floats):
//   sc : [0, 32768)            scores 32 x 1024
//   qs : [32768, 35072)        Q^T tile 64 x 36 (pitch 36, [d][m])
//   kv : [35072, 43776)        K chunk 64 x 132 ([d][n]) / V chunk 128 x 68 ([k][d])
#define SMEM_QS 32768
#define SMEM_KV 35072
#define ATTN_SMEM_FLOATS 43776
#define ATTN_SMEM_BYTES (ATTN_SMEM_FLOATS * 4)

__global__ __launch_bounds__(256)
void attn_kernel(const float* __restrict__ Q, const float* __restrict__ Kg,
                 const float* __restrict__ V, float* __restrict__ O) {
    extern __shared__ float sm[];
    float* sc = sm;                 // [32][1024]
    float* qs = sm + SMEM_QS;       // [64][36]  (qs[d][m])
    float* kv = sm + SMEM_KV;       // K: [64][132]  V: [128][68]

    int bh = blockIdx.y; int b = bh >> 4, h = bh & 15;
    int m0 = blockIdx.x * 32;
    const float* Qb = Q + (size_t)b * SS * DD + h * HDIM;
    const float* Kb = Kg + (size_t)b * SS * DD + h * HDIM;
    const float* Vb = V + (size_t)b * SS * DD + h * HDIM;

    int t = threadIdx.x, lane = t & 31;
    int ty = t >> 5;          // warp id 0..7 (uniform per warp)
    int tx = lane;            // 0..31

    // ---- load Q tile (32 rows x 64) transposed into qs[d][m] ----
    {
        int row = t >> 3;              // 0..31
        int cb = (t & 7) * 8;          // 0..56
#pragma unroll
        for (int i = 0; i < 2; i++) {
            float4 qv = *(const float4*)(Qb + (size_t)(m0 + row) * DD + cb + i * 4);
            qs[(cb + i * 4 + 0) * 36 + row] = qv.x;
            qs[(cb + i * 4 + 1) * 36 + row] = qv.y;
            qs[(cb + i * 4 + 2) * 36 + row] = qv.z;
            qs[(cb + i * 4 + 3) * 36 + row] = qv.w;
        }
    }
    __syncthreads();

    // ---- phase 1: scores sc[m][n] = ATT_SCALE * sum_d Q[m][d] K[n][d] ----
    // chunks of 128 n; K chunk staged transposed as kv[d][n] (pitch 132)
    for (int n0 = 0; n0 < SS; n0 += 128) {
        {
            int n = t & 127;                 // 0..127
            int dh = (t >> 7) * 32;          // 0 or 32
            const float* Kr = Kb + (size_t)(n0 + n) * DD + dh;
#pragma unroll
            for (int i = 0; i < 8; i++) {
                float4 kvv = *(const float4*)(Kr + i * 4);
                kv[(dh + i * 4 + 0) * 132 + n] = kvv.x;
                kv[(dh + i * 4 + 1) * 132 + n] = kvv.y;
                kv[(dh + i * 4 + 2) * 132 + n] = kvv.z;
                kv[(dh + i * 4 + 3) * 132 + n] = kvv.w;
            }
        }
        __syncthreads();
        float acc[4][4];
#pragma unroll
        for (int i = 0; i < 4; i++)
#pragma unroll
            for (int j = 0; j < 4; j++) acc[i][j] = 0.f;
#pragma unroll 8
        for (int d = 0; d < 64; d++) {
            float4 a = *(const float4*)&qs[d * 36 + ty * 4];     // broadcast (ty uniform)
            float4 bq = *(const float4*)&kv[d * 132 + tx * 4];   // conflict-free
            float ar[4] = {a.x, a.y, a.z, a.w};
            float br[4] = {bq.x, bq.y, bq.z, bq.w};
#pragma unroll
            for (int i = 0; i < 4; i++)
#pragma unroll
                for (int j = 0; j < 4; j++) acc[i][j] = fmaf(ar[i], br[j], acc[i][j]);
        }
#pragma unroll
        for (int i = 0; i < 4; i++) {
            float4 outv = make_float4(acc[i][0] * ATT_SCALE, acc[i][1] * ATT_SCALE,
                                      acc[i][2] * ATT_SCALE, acc[i][3] * ATT_SCALE);
            *(float4*)&sc[(ty * 4 + i) * SS + n0 + tx * 4] = outv;   // conflict-free
        }
        __syncthreads();
    }

    // ---- phase 2: exact 1.5-entmax per row (warp w owns rows 4w..4w+3) ----
    {
#pragma unroll 1
        for (int r = 0; r < 4; r++) {
            float* z = sc + (size_t)(ty * 4 + r) * SS;
            float v[32];
#pragma unroll
            for (int i = 0; i < 32; i++) v[i] = z[lane + 32 * i];
            float m = -1e30f;
#pragma unroll
            for (int i = 0; i < 32; i++) m = fmaxf(m, v[i]);
            m = warpMax(m);
#pragma unroll
            for (int i = 0; i < 32; i++) v[i] = (v[i] - m) * 0.5f;
            // f(tau) = sum relu(v - tau)^2 decreasing; f(-1) >= 1 >= f(0); bisect.
            float lo = -1.f, hi = 0.f;
            for (int it = 0; it < 30; it++) {
                float tau = 0.5f * (lo + hi);
                float s = 0.f;
#pragma unroll
                for (int i = 0; i < 32; i++) {
                    float d = v[i] - tau;
                    if (d > 0.f) s = fmaf(d, d, s);
                }
                s = warpSum(s);
                if (s >= 1.f) lo = tau; else hi = tau;
            }
            float tau = 0.5f * (lo + hi);
#pragma unroll
            for (int i = 0; i < 32; i++) {
                float d = v[i] - tau;
                d = d > 0.f ? d : 0.f;
                z[lane + 32 * i] = d * d;
            }
        }
    }
    __syncthreads();

    // ---- phase 3: O[m][d] = sum_k P[m][k] V[k][d]; V chunk staged as kv[k][d] p68 ----
    float oacc[4][2];
#pragma unroll
    for (int i = 0; i < 4; i++) { oacc[i][0] = 0.f; oacc[i][1] = 0.f; }

    for (int k0 = 0; k0 < SS; k0 += 128) {
        {
            int r = t >> 1;                 // 0..127
            int ch = (t & 1) * 32;          // 0 or 32
            const float* Vr = Vb + (size_t)(k0 + r) * DD + ch;
#pragma unroll
            for (int i = 0; i < 8; i++)
                *(float4*)&kv[r * 68 + ch + i * 4] = *(const float4*)(Vr + i * 4);
        }
        __syncthreads();
#pragma unroll 4
        for (int kk = 0; kk < 128; kk++) {
            float b0 = kv[kk * 68 + tx];        // conflict-free
            float b1 = kv[kk * 68 + tx + 32];
#pragma unroll
            for (int i = 0; i < 4; i++) {
                float a = sc[(ty * 4 + i) * SS + k0 + kk];   // broadcast
                oacc[i][0] = fmaf(a, b0, oacc[i][0]);
                oacc[i][1] = fmaf(a, b1, oacc[i][1]);
            }
        }
        __syncthreads();
    }
    float* Ob = O + (size_t)b * SS * DD + h * HDIM;
#pragma unroll
    for (int i = 0; i < 4; i++) {
        Ob[(size_t)(m0 + ty * 4 + i) * DD + tx]      = oacc[i][0];
        Ob[(size_t)(m0 + ty * 4 + i) * DD + tx + 32] = oacc[i][1];
    }
}

// ---------------- launch ----------------
extern "C" void kernel_launch(void* const* d_in, const int* in_sizes, int n_in,
                              void* d_out, int out_size) {
    const float* x = (const float*)d_in[0];
    const float *wq, *bq, *wk, *bk, *wv, *bv, *wo, *bo;
    if (in_sizes[2] == DD) {
        // reference-signature order: x, wq, bq, wk, bk, wv, bv, wo, bo, ...
        wq = (const float*)d_in[1]; bq = (const float*)d_in[2];
        wk = (const float*)d_in[3]; bk = (const float*)d_in[4];
        wv = (const float*)d_in[5]; bv = (const float*)d_in[6];
        wo = (const float*)d_in[7]; bo = (const float*)d_in[8];
    } else {
        // setup_inputs dict order: x, wq, wk, wv, wo, bq, bk, bv, bo, ...
        wq = (const float*)d_in[1]; wk = (const float*)d_in[2];
        wv = (const float*)d_in[3]; wo = (const float*)d_in[4];
        bq = (const float*)d_in[5]; bk = (const float*)d_in[6];
        bv = (const float*)d_in[7]; bo = (const float*)d_in[8];
    }
    const float* w_up   = (const float*)d_in[9];
    const float* b_up   = (const float*)d_in[10];
    const float* w_down = (const float*)d_in[11];
    const float* b_down = (const float*)d_in[12];
    const float* ln1g = (const float*)d_in[13];
    const float* ln1b = (const float*)d_in[14];
    const float* ln2g = (const float*)d_in[15];
    const float* ln2b = (const float*)d_in[16];
    const float* lnfg = (const float*)d_in[17];
    const float* lnfb = (const float*)d_in[18];

    float *yp, *qp, *kp, *vp, *x1p, *hp;
    cudaGetSymbolAddress((void**)&yp,  g_y);
    cudaGetSymbolAddress((void**)&qp,  g_q);
    cudaGetSymbolAddress((void**)&kp,  g_k);
    cudaGetSymbolAddress((void**)&vp,  g_v);
    cudaGetSymbolAddress((void**)&x1p, g_x1);
    cudaGetSymbolAddress((void**)&hp,  g_h);
    float* op  = yp;   // reuse: y dead after V projection
    float* x2p = qp;   // reuse: q dead after attention

    cudaFuncSetAttribute(attn_kernel, cudaFuncAttributeMaxDynamicSharedMemorySize,
                         ATTN_SMEM_BYTES);

    // 1. ln1
    ln_kernel<<<NROWS, 256>>>(x, ln1g, ln1b, yp);
    // 2-4. Q,K,V projections
    sgemm_kernel<0><<<dim3(8, 32), 256>>>(yp, wq, bq, nullptr, qp, NROWS, DD, DD);
    sgemm_kernel<0><<<dim3(8, 32), 256>>>(yp, wk, bk, nullptr, kp, NROWS, DD, DD);
    sgemm_kernel<0><<<dim3(8, 32), 256>>>(yp, wv, bv, nullptr, vp, NROWS, DD, DD);
    // 5. fused attention (scores + 1.5-entmax + P@V); writes op (= yp, y now dead)
    attn_kernel<<<dim3(SS / 32, NHEADS), 256, ATTN_SMEM_BYTES>>>(qp, kp, vp, op);
    // 6. out proj + residual
    sgemm_kernel<2><<<dim3(8, 32), 256>>>(op, wo, bo, x, x1p, NROWS, DD, DD);
    // 7. ln2 -> k scratch (k dead)
    ln_kernel<<<NROWS, 256>>>(x1p, ln2g, ln2b, kp);
    // 8. FFN up + mish
    sgemm_kernel<1><<<dim3(32, 32), 256>>>(kp, w_up, b_up, nullptr, hp, NROWS, FF, DD);
    // 9. FFN down + residual (writes x2p = qp, q dead)
    sgemm_kernel<2><<<dim3(8, 32), 256>>>(hp, w_down, b_down, x1p, x2p, NROWS, DD, FF);
    // 10. final ln -> out
    ln_kernel<<<NROWS, 256>>>(x2p, lnfg, lnfb, (float*)d_out);
}

// round 4
// speedup vs baseline: 1.6793x; 1.6793x over previous
#include <cuda_runtime.h>
#include <math.h>
#include <stdint.h>

#define BB 4
#define SS 1024
#define DD 1024
#define HH 16
#define HDIM 64
#define FF 4096
#define NROWS (BB*SS)           // 4096
#define NHEADS (BB*HH)          // 64
#define LN_EPS 1e-5f
#define ATT_SCALE 0.125f        // 1/sqrt(64)

// ---------------- scratch (static device arrays; no cudaMalloc allowed) --------------
__device__ float g_y [NROWS*DD];   // ln1 out, later attention output
__device__ float g_q [NROWS*DD];   // Q, later x2 (post-FFN residual)
__device__ float g_k [NROWS*DD];
__device__ float g_v [NROWS*DD];
__device__ float g_x1[NROWS*DD];   // post-attention residual
__device__ float g_h [NROWS*FF];   // FFN hidden

// ---------------- reduction helpers ----------------
__device__ __forceinline__ float warpSum(float v) {
#pragma unroll
    for (int o = 16; o > 0; o >>= 1) v += __shfl_xor_sync(0xffffffffu, v, o);
    return v;
}
__device__ __forceinline__ float warpMax(float v) {
#pragma unroll
    for (int o = 16; o > 0; o >>= 1) v = fmaxf(v, __shfl_xor_sync(0xffffffffu, v, o));
    return v;
}

// ---------------- LayerNorm over D=1024, one block (256 thr) per row -----------------
__global__ void ln_kernel(const float* __restrict__ in, const float* __restrict__ g,
                          const float* __restrict__ b, float* __restrict__ out) {
    int row = blockIdx.x;
    const float* x = in + (size_t)row * DD;
    int t = threadIdx.x, lane = t & 31, wid = t >> 5;
    float v[4];
#pragma unroll
    for (int i = 0; i < 4; i++) v[i] = x[t + 256 * i];
    float s = v[0] + v[1] + v[2] + v[3];
    float ss = v[0]*v[0] + v[1]*v[1] + v[2]*v[2] + v[3]*v[3];
    s = warpSum(s); ss = warpSum(ss);
    __shared__ float rA[8], rB[8];
    if (lane == 0) { rA[wid] = s; rB[wid] = ss; }
    __syncthreads();
    s  = (lane < 8) ? rA[lane] : 0.f;
    ss = (lane < 8) ? rB[lane] : 0.f;
    s = warpSum(s); ss = warpSum(ss);
    float mean = s * (1.f / DD);
    float var  = ss * (1.f / DD) - mean * mean;
    float rstd = rsqrtf(var + LN_EPS);
    float* o = out + (size_t)row * DD;
#pragma unroll
    for (int i = 0; i < 4; i++) {
        int c = t + 256 * i;
        o[c] = (v[i] - mean) * rstd * g[c] + b[c];
    }
}

// ---------------- mish ----------------
__device__ __forceinline__ float mishf(float x) {
    float sp = (x > 20.f) ? x : log1pf(expf(x));
    return x * tanhf(sp);
}

// ---------------- tf32 helpers ----------------
__device__ __forceinline__ uint32_t f2tf32(float x) {
    uint32_t r;
    asm("cvt.rna.tf32.f32 %0, %1;" : "=r"(r) : "f"(x));
    return r;
}
__device__ __forceinline__ void mma_tf32(float* c, const uint32_t* a, const uint32_t* b) {
    asm volatile(
        "mma.sync.aligned.m16n8k8.row.col.f32.tf32.tf32.f32 "
        "{%0,%1,%2,%3}, {%4,%5,%6,%7}, {%8,%9}, {%0,%1,%2,%3};\n"
        : "+f"(c[0]), "+f"(c[1]), "+f"(c[2]), "+f"(c[3])
        : "r"(a[0]), "r"(a[1]), "r"(a[2]), "r"(a[3]), "r"(b[0]), "r"(b[1]));
}

// ---------------- tf32 tensor-core GEMM: C = epi(A[M,K] @ W[K,N] + bias[N]) ----------
// Block tile 128x128, BK=32. 8 warps in 2(m) x 4(n): each warp 64x32 = 4x4 m16n8k8.
// smem pitch 136 (pad 8 mod 32) -> fragment gathers (8*tig + g) are conflict-free.
// EPI: 0 = bias only, 1 = bias + mish, 2 = bias + residual add
template <int EPI>
__global__ __launch_bounds__(256)
void tgemm_kernel(const float* __restrict__ A, const float* __restrict__ W,
                  const float* __restrict__ bias, const float* __restrict__ resid,
                  float* __restrict__ C, int M, int N, int K) {
    __shared__ uint32_t As[32][136];   // [k][m]
    __shared__ uint32_t Bs[32][136];   // [k][n]
    int tid = threadIdx.x, lane = tid & 31, wid = tid >> 5;
    int g = lane >> 2, tig = lane & 3;
    int wm = (wid >> 2) * 64, wn = (wid & 3) * 32;
    int bm = blockIdx.y * 128, bn = blockIdx.x * 128;

    float acc[4][4][4];
#pragma unroll
    for (int mt = 0; mt < 4; mt++)
#pragma unroll
        for (int nt = 0; nt < 4; nt++)
#pragma unroll
            for (int i = 0; i < 4; i++) acc[mt][nt][i] = 0.f;

    int aRow = tid >> 1, aColB = (tid & 1) * 4;
    int bRow = tid >> 3, bColB = (tid & 7) * 4;
    const float* Ab = A + (size_t)(bm + aRow) * K;
    const float* Wb = W + (size_t)bRow * N + bn;

    for (int k0 = 0; k0 < K; k0 += 32) {
        // stage A tile transposed: As[k][m], converting to tf32
#pragma unroll
        for (int p = 0; p < 4; p++) {
            float4 av = *(const float4*)(Ab + k0 + aColB + p * 8);
            int kk = aColB + p * 8;
            As[kk + 0][aRow] = f2tf32(av.x);
            As[kk + 1][aRow] = f2tf32(av.y);
            As[kk + 2][aRow] = f2tf32(av.z);
            As[kk + 3][aRow] = f2tf32(av.w);
        }
        // stage B tile: Bs[k][n]
#pragma unroll
        for (int p = 0; p < 4; p++) {
            float4 bv = *(const float4*)(Wb + (size_t)k0 * N + bColB + p * 32);
            uint32_t* dst = &Bs[bRow][bColB + p * 32];
            dst[0] = f2tf32(bv.x); dst[1] = f2tf32(bv.y);
            dst[2] = f2tf32(bv.z); dst[3] = f2tf32(bv.w);
        }
        __syncthreads();
#pragma unroll
        for (int kt = 0; kt < 4; kt++) {
            int kb = kt * 8;
            uint32_t af[4][4], bf[4][2];
#pragma unroll
            for (int mt = 0; mt < 4; mt++) {
                int m = wm + mt * 16 + g;
                af[mt][0] = As[kb + tig][m];
                af[mt][1] = As[kb + tig][m + 8];
                af[mt][2] = As[kb + tig + 4][m];
                af[mt][3] = As[kb + tig + 4][m + 8];
            }
#pragma unroll
            for (int nt = 0; nt < 4; nt++) {
                int n = wn + nt * 8 + g;
                bf[nt][0] = Bs[kb + tig][n];
                bf[nt][1] = Bs[kb + tig + 4][n];
            }
#pragma unroll
            for (int mt = 0; mt < 4; mt++)
#pragma unroll
                for (int nt = 0; nt < 4; nt++)
                    mma_tf32(acc[mt][nt], af[mt], bf[nt]);
        }
        __syncthreads();
    }

    // epilogue: c0:(g,tig*2) c1:(g,tig*2+1) c2:(g+8,tig*2) c3:(g+8,tig*2+1)
#pragma unroll
    for (int mt = 0; mt < 4; mt++) {
        int row0 = bm + wm + mt * 16 + g;
#pragma unroll
        for (int nt = 0; nt < 4; nt++) {
            int col = bn + wn + nt * 8 + tig * 2;
            float b0 = bias[col], b1 = bias[col + 1];
#pragma unroll
            for (int half = 0; half < 2; half++) {
                int row = row0 + half * 8;
                float v0 = acc[mt][nt][half * 2 + 0] + b0;
                float v1 = acc[mt][nt][half * 2 + 1] + b1;
                if (EPI == 1) { v0 = mishf(v0); v1 = mishf(v1); }
                if (EPI == 2) {
                    v0 += resid[(size_t)row * N + col];
                    v1 += resid[(size_t)row * N + col + 1];
                }
                C[(size_t)row * N + col]     = v0;
                C[(size_t)row * N + col + 1] = v1;
            }
        }
    }
}

// ---------------- fused attention: scores + exact 1.5-entmax + P@V -------------------
// One block per (32-query tile, head). Full 32x1024 score rows live in smem.
#define SMEM_QS 32768
#define SMEM_KV 35072
#define ATTN_SMEM_FLOATS 43776
#define ATTN_SMEM_BYTES (ATTN_SMEM_FLOATS * 4)

__global__ __launch_bounds__(256)
void attn_kernel(const float* __restrict__ Q, const float* __restrict__ Kg,
                 const float* __restrict__ V, float* __restrict__ O) {
    extern __shared__ float sm[];
    float* sc = sm;                 // [32][1024]
    float* qs = sm + SMEM_QS;       // [64][36]  (qs[d][m])
    float* kv = sm + SMEM_KV;       // K: [64][132]  V: [128][68]

    int bh = blockIdx.y; int b = bh >> 4, h = bh & 15;
    int m0 = blockIdx.x * 32;
    const float* Qb = Q + (size_t)b * SS * DD + h * HDIM;
    const float* Kb = Kg + (size_t)b * SS * DD + h * HDIM;
    const float* Vb = V + (size_t)b * SS * DD + h * HDIM;

    int t = threadIdx.x, lane = t & 31;
    int ty = t >> 5;          // warp id 0..7 (uniform per warp)
    int tx = lane;            // 0..31

    // ---- load Q tile (32 rows x 64) transposed into qs[d][m] ----
    {
        int row = t >> 3;              // 0..31
        int cb = (t & 7) * 8;          // 0..56
#pragma unroll
        for (int i = 0; i < 2; i++) {
            float4 qv = *(const float4*)(Qb + (size_t)(m0 + row) * DD + cb + i * 4);
            qs[(cb + i * 4 + 0) * 36 + row] = qv.x;
            qs[(cb + i * 4 + 1) * 36 + row] = qv.y;
            qs[(cb + i * 4 + 2) * 36 + row] = qv.z;
            qs[(cb + i * 4 + 3) * 36 + row] = qv.w;
        }
    }
    __syncthreads();

    // ---- phase 1: scores sc[m][n] = ATT_SCALE * sum_d Q[m][d] K[n][d] ----
    for (int n0 = 0; n0 < SS; n0 += 128) {
        {
            int n = t & 127;                 // 0..127
            int dh = (t >> 7) * 32;          // 0 or 32
            const float* Kr = Kb + (size_t)(n0 + n) * DD + dh;
#pragma unroll
            for (int i = 0; i < 8; i++) {
                float4 kvv = *(const float4*)(Kr + i * 4);
                kv[(dh + i * 4 + 0) * 132 + n] = kvv.x;
                kv[(dh + i * 4 + 1) * 132 + n] = kvv.y;
                kv[(dh + i * 4 + 2) * 132 + n] = kvv.z;
                kv[(dh + i * 4 + 3) * 132 + n] = kvv.w;
            }
        }
        __syncthreads();
        float acc[4][4];
#pragma unroll
        for (int i = 0; i < 4; i++)
#pragma unroll
            for (int j = 0; j < 4; j++) acc[i][j] = 0.f;
#pragma unroll 8
        for (int d = 0; d < 64; d++) {
            float4 a = *(const float4*)&qs[d * 36 + ty * 4];     // broadcast (ty uniform)
            float4 bq = *(const float4*)&kv[d * 132 + tx * 4];   // conflict-free
            float ar[4] = {a.x, a.y, a.z, a.w};
            float br[4] = {bq.x, bq.y, bq.z, bq.w};
#pragma unroll
            for (int i = 0; i < 4; i++)
#pragma unroll
                for (int j = 0; j < 4; j++) acc[i][j] = fmaf(ar[i], br[j], acc[i][j]);
        }
#pragma unroll
        for (int i = 0; i < 4; i++) {
            float4 outv = make_float4(acc[i][0] * ATT_SCALE, acc[i][1] * ATT_SCALE,
                                      acc[i][2] * ATT_SCALE, acc[i][3] * ATT_SCALE);
            *(float4*)&sc[(ty * 4 + i) * SS + n0 + tx * 4] = outv;   // conflict-free
        }
        __syncthreads();
    }

    // ---- phase 2: exact 1.5-entmax per row (warp w owns rows 4w..4w+3) ----
    {
#pragma unroll 1
        for (int r = 0; r < 4; r++) {
            float* z = sc + (size_t)(ty * 4 + r) * SS;
            float v[32];
#pragma unroll
            for (int i = 0; i < 32; i++) v[i] = z[lane + 32 * i];
            float m = -1e30f;
#pragma unroll
            for (int i = 0; i < 32; i++) m = fmaxf(m, v[i]);
            m = warpMax(m);
#pragma unroll
            for (int i = 0; i < 32; i++) v[i] = (v[i] - m) * 0.5f;
            float lo = -1.f, hi = 0.f;
            for (int it = 0; it < 30; it++) {
                float tau = 0.5f * (lo + hi);
                float s = 0.f;
#pragma unroll
                for (int i = 0; i < 32; i++) {
                    float d = v[i] - tau;
                    if (d > 0.f) s = fmaf(d, d, s);
                }
                s = warpSum(s);
                if (s >= 1.f) lo = tau; else hi = tau;
            }
            float tau = 0.5f * (lo + hi);
#pragma unroll
            for (int i = 0; i < 32; i++) {
                float d = v[i] - tau;
                d = d > 0.f ? d : 0.f;
                z[lane + 32 * i] = d * d;
            }
        }
    }
    __syncthreads();

    // ---- phase 3: O[m][d] = sum_k P[m][k] V[k][d] ----
    float oacc[4][2];
#pragma unroll
    for (int i = 0; i < 4; i++) { oacc[i][0] = 0.f; oacc[i][1] = 0.f; }

    for (int k0 = 0; k0 < SS; k0 += 128) {
        {
            int r = t >> 1;                 // 0..127
            int ch = (t & 1) * 32;          // 0 or 32
            const float* Vr = Vb + (size_t)(k0 + r) * DD + ch;
#pragma unroll
            for (int i = 0; i < 8; i++)
                *(float4*)&kv[r * 68 + ch + i * 4] = *(const float4*)(Vr + i * 4);
        }
        __syncthreads();
#pragma unroll 4
        for (int kk = 0; kk < 128; kk++) {
            float b0 = kv[kk * 68 + tx];
            float b1 = kv[kk * 68 + tx + 32];
#pragma unroll
            for (int i = 0; i < 4; i++) {
                float a = sc[(ty * 4 + i) * SS + k0 + kk];
                oacc[i][0] = fmaf(a, b0, oacc[i][0]);
                oacc[i][1] = fmaf(a, b1, oacc[i][1]);
            }
        }
        __syncthreads();
    }
    float* Ob = O + (size_t)b * SS * DD + h * HDIM;
#pragma unroll
    for (int i = 0; i < 4; i++) {
        Ob[(size_t)(m0 + ty * 4 + i) * DD + tx]      = oacc[i][0];
        Ob[(size_t)(m0 + ty * 4 + i) * DD + tx + 32] = oacc[i][1];
    }
}

// ---------------- launch ----------------
extern "C" void kernel_launch(void* const* d_in, const int* in_sizes, int n_in,
                              void* d_out, int out_size) {
    const float* x = (const float*)d_in[0];
    const float *wq, *bq, *wk, *bk, *wv, *bv, *wo, *bo;
    if (in_sizes[2] == DD) {
        wq = (const float*)d_in[1]; bq = (const float*)d_in[2];
        wk = (const float*)d_in[3]; bk = (const float*)d_in[4];
        wv = (const float*)d_in[5]; bv = (const float*)d_in[6];
        wo = (const float*)d_in[7]; bo = (const float*)d_in[8];
    } else {
        wq = (const float*)d_in[1]; wk = (const float*)d_in[2];
        wv = (const float*)d_in[3]; wo = (const float*)d_in[4];
        bq = (const float*)d_in[5]; bk = (const float*)d_in[6];
        bv = (const float*)d_in[7]; bo = (const float*)d_in[8];
    }
    const float* w_up   = (const float*)d_in[9];
    const float* b_up   = (const float*)d_in[10];
    const float* w_down = (const float*)d_in[11];
    const float* b_down = (const float*)d_in[12];
    const float* ln1g = (const float*)d_in[13];
    const float* ln1b = (const float*)d_in[14];
    const float* ln2g = (const float*)d_in[15];
    const float* ln2b = (const float*)d_in[16];
    const float* lnfg = (const float*)d_in[17];
    const float* lnfb = (const float*)d_in[18];

    float *yp, *qp, *kp, *vp, *x1p, *hp;
    cudaGetSymbolAddress((void**)&yp,  g_y);
    cudaGetSymbolAddress((void**)&qp,  g_q);
    cudaGetSymbolAddress((void**)&kp,  g_k);
    cudaGetSymbolAddress((void**)&vp,  g_v);
    cudaGetSymbolAddress((void**)&x1p, g_x1);
    cudaGetSymbolAddress((void**)&hp,  g_h);
    float* op  = yp;   // reuse: y dead after V projection
    float* x2p = qp;   // reuse: q dead after attention

    cudaFuncSetAttribute(attn_kernel, cudaFuncAttributeMaxDynamicSharedMemorySize,
                         ATTN_SMEM_BYTES);

    // 1. ln1
    ln_kernel<<<NROWS, 256>>>(x, ln1g, ln1b, yp);
    // 2-4. Q,K,V projections (tf32 tensor cores)
    tgemm_kernel<0><<<dim3(8, 32), 256>>>(yp, wq, bq, nullptr, qp, NROWS, DD, DD);
    tgemm_kernel<0><<<dim3(8, 32), 256>>>(yp, wk, bk, nullptr, kp, NROWS, DD, DD);
    tgemm_kernel<0><<<dim3(8, 32), 256>>>(yp, wv, bv, nullptr, vp, NROWS, DD, DD);
    // 5. fused attention (scores + 1.5-entmax + P@V)
    attn_kernel<<<dim3(SS / 32, NHEADS), 256, ATTN_SMEM_BYTES>>>(qp, kp, vp, op);
    // 6. out proj + residual
    tgemm_kernel<2><<<dim3(8, 32), 256>>>(op, wo, bo, x, x1p, NROWS, DD, DD);
    // 7. ln2 -> k scratch (k dead)
    ln_kernel<<<NROWS, 256>>>(x1p, ln2g, ln2b, kp);
    // 8. FFN up + mish
    tgemm_kernel<1><<<dim3(32, 32), 256>>>(kp, w_up, b_up, nullptr, hp, NROWS, FF, DD);
    // 9. FFN down + residual
    tgemm_kernel<2><<<dim3(8, 32), 256>>>(hp, w_down, b_down, x1p, x2p, NROWS, DD, FF);
    // 10. final ln -> out
    ln_kernel<<<NROWS, 256>>>(x2p, lnfg, lnfb, (float*)d_out);
}